// round 1
// baseline (speedup 1.0000x reference)
#include <cuda_runtime.h>
#include <cuda_bf16.h>
#include <math.h>

#define B_ 4
#define N_ 2048
#define C_ 512
#define H_ 8
#define HD_ 64
#define HIDE_ 2048
#define M_ (B_ * N_)   // 8192 rows

// Scratch (device globals: no cudaMalloc allowed)
__device__ float g_attn[(size_t)M_ * C_];     // attention out; later reused for pre-LN2 sum
__device__ float g_q2[(size_t)M_ * C_];       // LN1 output
__device__ float g_h[(size_t)M_ * HIDE_];     // fc1+gelu output

// ---------------------------------------------------------------------------
// Flash attention: one block per (q-tile of 64, head, batch). 256 threads.
// S tile 64x64, 4x4 per thread, online softmax.
// smem: Qs [64d][68] transposed, Ks [64d][68] transposed (reused as P [c][68->r]),
//       Vs [64c][68] natural.
// ---------------------------------------------------------------------------
#define ATTN_STRIDE 68
#define ATTN_SMEM (3 * 64 * ATTN_STRIDE * 4)

__global__ void attn_kernel(const float* __restrict__ q,
                            const float* __restrict__ k,
                            const float* __restrict__ v,
                            float* __restrict__ out)
{
    extern __shared__ float sm[];
    float* Qs = sm;                       // [d][r]
    float* Ks = sm + 64 * ATTN_STRIDE;    // [d][c], later P as [c][r]
    float* Vs = sm + 2 * 64 * ATTN_STRIDE;// [c][d]

    const int tid = threadIdx.x;
    const int ty = tid >> 4;      // 0..15  (row group)
    const int tx = tid & 15;      // 0..15  (col group)

    const int b = blockIdx.z;
    const int h = blockIdx.y;
    const int qt = blockIdx.x;

    const float* Qg = q + ((size_t)(b * N_ + qt * 64)) * C_ + h * HD_;
    const float* Kg = k + (size_t)b * N_ * C_ + h * HD_;
    const float* Vg = v + (size_t)b * N_ * C_ + h * HD_;

    // Load Q tile (scaled by 1/sqrt(64)=0.125), transposed into Qs[d][r]
    for (int i = tid; i < 64 * 16; i += 256) {
        int r = i >> 4;
        int dq = (i & 15) * 4;
        float4 t = *(const float4*)(Qg + (size_t)r * C_ + dq);
        Qs[(dq + 0) * ATTN_STRIDE + r] = t.x * 0.125f;
        Qs[(dq + 1) * ATTN_STRIDE + r] = t.y * 0.125f;
        Qs[(dq + 2) * ATTN_STRIDE + r] = t.z * 0.125f;
        Qs[(dq + 3) * ATTN_STRIDE + r] = t.w * 0.125f;
    }

    float m_i[4], l_i[4], acc[4][4];
#pragma unroll
    for (int i = 0; i < 4; i++) {
        m_i[i] = -1e30f;
        l_i[i] = 0.0f;
#pragma unroll
        for (int j = 0; j < 4; j++) acc[i][j] = 0.0f;
    }

    for (int kt = 0; kt < N_ / 64; kt++) {
        __syncthreads();  // protect Ks/Vs (and Qs on first iter) from prior readers

        const float* Kt = Kg + (size_t)kt * 64 * C_;
        const float* Vt = Vg + (size_t)kt * 64 * C_;
        for (int i = tid; i < 64 * 16; i += 256) {
            int c = i >> 4;
            int dq = (i & 15) * 4;
            float4 t = *(const float4*)(Kt + (size_t)c * C_ + dq);
            Ks[(dq + 0) * ATTN_STRIDE + c] = t.x;
            Ks[(dq + 1) * ATTN_STRIDE + c] = t.y;
            Ks[(dq + 2) * ATTN_STRIDE + c] = t.z;
            Ks[(dq + 3) * ATTN_STRIDE + c] = t.w;
            float4 u = *(const float4*)(Vt + (size_t)c * C_ + dq);
            *(float4*)(Vs + c * ATTN_STRIDE + dq) = u;
        }
        __syncthreads();

        // S = Q K^T  (scaled Q)
        float s[4][4];
#pragma unroll
        for (int i = 0; i < 4; i++)
#pragma unroll
            for (int j = 0; j < 4; j++) s[i][j] = 0.0f;

#pragma unroll 16
        for (int kk = 0; kk < 64; kk++) {
            float4 a = *(const float4*)(Qs + kk * ATTN_STRIDE + ty * 4);
            float4 bb = *(const float4*)(Ks + kk * ATTN_STRIDE + tx * 4);
            float ar[4] = {a.x, a.y, a.z, a.w};
            float br[4] = {bb.x, bb.y, bb.z, bb.w};
#pragma unroll
            for (int i = 0; i < 4; i++)
#pragma unroll
                for (int j = 0; j < 4; j++) s[i][j] = fmaf(ar[i], br[j], s[i][j]);
        }

        // Online softmax (row reductions across tx group: 16 lanes of same half-warp)
#pragma unroll
        for (int i = 0; i < 4; i++) {
            float mx = fmaxf(fmaxf(s[i][0], s[i][1]), fmaxf(s[i][2], s[i][3]));
#pragma unroll
            for (int off = 8; off >= 1; off >>= 1)
                mx = fmaxf(mx, __shfl_xor_sync(0xffffffffu, mx, off));
            float mnew = fmaxf(m_i[i], mx);
            float sum = 0.0f;
#pragma unroll
            for (int j = 0; j < 4; j++) {
                s[i][j] = __expf(s[i][j] - mnew);
                sum += s[i][j];
            }
#pragma unroll
            for (int off = 8; off >= 1; off >>= 1)
                sum += __shfl_xor_sync(0xffffffffu, sum, off);
            float corr = __expf(m_i[i] - mnew);
            l_i[i] = l_i[i] * corr + sum;
            m_i[i] = mnew;
#pragma unroll
            for (int j = 0; j < 4; j++) acc[i][j] *= corr;
        }

        __syncthreads();  // everyone done reading Ks before overwrite with P

        // Write P into Ks region as Ps[c][r]
#pragma unroll
        for (int j = 0; j < 4; j++)
#pragma unroll
            for (int i = 0; i < 4; i++)
                Ks[(tx * 4 + j) * ATTN_STRIDE + ty * 4 + i] = s[i][j];
        __syncthreads();

        // O += P @ V
#pragma unroll 16
        for (int kk = 0; kk < 64; kk++) {
            float4 a = *(const float4*)(Ks + kk * ATTN_STRIDE + ty * 4);
            float4 bb = *(const float4*)(Vs + kk * ATTN_STRIDE + tx * 4);
            float ar[4] = {a.x, a.y, a.z, a.w};
            float br[4] = {bb.x, bb.y, bb.z, bb.w};
#pragma unroll
            for (int i = 0; i < 4; i++)
#pragma unroll
                for (int j = 0; j < 4; j++) acc[i][j] = fmaf(ar[i], br[j], acc[i][j]);
        }
    }

    // Epilogue: normalize and store
    float* Og = out + ((size_t)(b * N_ + qt * 64)) * C_ + h * HD_;
#pragma unroll
    for (int i = 0; i < 4; i++) {
        float inv = 1.0f / l_i[i];
        float4 o;
        o.x = acc[i][0] * inv;
        o.y = acc[i][1] * inv;
        o.z = acc[i][2] * inv;
        o.w = acc[i][3] * inv;
        *(float4*)(Og + (size_t)(ty * 4 + i) * C_ + tx * 4) = o;
    }
}

// ---------------------------------------------------------------------------
// Fused (optional residual add) + LayerNorm. One block (128 thr) per row, C=512.
// ---------------------------------------------------------------------------
__global__ void ln_kernel(const float* __restrict__ x,
                          const float* __restrict__ res,
                          const float* __restrict__ w,
                          const float* __restrict__ bb,
                          float* __restrict__ out)
{
    const int row = blockIdx.x;
    const int tid = threadIdx.x;
    const int col = tid * 4;

    float4 a = *(const float4*)(x + (size_t)row * C_ + col);
    if (res != nullptr) {
        float4 r4 = *(const float4*)(res + (size_t)row * C_ + col);
        a.x += r4.x; a.y += r4.y; a.z += r4.z; a.w += r4.w;
    }
    float s = a.x + a.y + a.z + a.w;
    float ss = a.x * a.x + a.y * a.y + a.z * a.z + a.w * a.w;

#pragma unroll
    for (int off = 16; off >= 1; off >>= 1) {
        s += __shfl_xor_sync(0xffffffffu, s, off);
        ss += __shfl_xor_sync(0xffffffffu, ss, off);
    }
    __shared__ float red[8];
    int wid = tid >> 5;
    if ((tid & 31) == 0) { red[wid] = s; red[wid + 4] = ss; }
    __syncthreads();
    float tot = red[0] + red[1] + red[2] + red[3];
    float tot2 = red[4] + red[5] + red[6] + red[7];

    const float mean = tot * (1.0f / C_);
    const float var = tot2 * (1.0f / C_) - mean * mean;
    const float inv = rsqrtf(var + 1e-6f);

    float4 wv = *(const float4*)(w + col);
    float4 bv = *(const float4*)(bb + col);
    float4 o;
    o.x = (a.x - mean) * inv * wv.x + bv.x;
    o.y = (a.y - mean) * inv * wv.y + bv.y;
    o.z = (a.z - mean) * inv * wv.z + bv.z;
    o.w = (a.w - mean) * inv * wv.w + bv.w;
    *(float4*)(out + (size_t)row * C_ + col) = o;
}

// ---------------------------------------------------------------------------
// SGEMM: out[m][n] = epi( sum_k A[m][k] * W[n][k] + bias[n] )
// 128x128 tile, BK=16, 256 threads, 8x8 per thread.
// EPI==0: GELU(exact).  EPI==1: + resid[m][n].
// ---------------------------------------------------------------------------
#define GBM 128
#define GBN 128
#define GBK 16

template <int EPI>
__global__ void gemm_kernel(const float* __restrict__ A,
                            const float* __restrict__ W,
                            const float* __restrict__ bias,
                            const float* __restrict__ resid,
                            float* __restrict__ out,
                            int Mdim, int Ndim, int Kdim)
{
    __shared__ float As[GBK][GBM];
    __shared__ float Bs[GBK][GBN];

    const int tid = threadIdx.x;
    const int m0 = blockIdx.y * GBM;
    const int n0 = blockIdx.x * GBN;
    const int ty = tid >> 4;
    const int tx = tid & 15;

    float acc[8][8];
#pragma unroll
    for (int i = 0; i < 8; i++)
#pragma unroll
        for (int j = 0; j < 8; j++) acc[i][j] = 0.0f;

    const float* Ab = A + (size_t)m0 * Kdim;
    const float* Wb = W + (size_t)n0 * Kdim;

    for (int k0 = 0; k0 < Kdim; k0 += GBK) {
#pragma unroll
        for (int c = 0; c < 2; c++) {
            int idx = c * 256 + tid;
            int row = idx >> 2;
            int kk = (idx & 3) * 4;
            float4 av = *(const float4*)(Ab + (size_t)row * Kdim + k0 + kk);
            As[kk + 0][row] = av.x;
            As[kk + 1][row] = av.y;
            As[kk + 2][row] = av.z;
            As[kk + 3][row] = av.w;
            float4 bv = *(const float4*)(Wb + (size_t)row * Kdim + k0 + kk);
            Bs[kk + 0][row] = bv.x;
            Bs[kk + 1][row] = bv.y;
            Bs[kk + 2][row] = bv.z;
            Bs[kk + 3][row] = bv.w;
        }
        __syncthreads();

#pragma unroll
        for (int kk = 0; kk < GBK; kk++) {
            float4 a0 = *(const float4*)&As[kk][ty * 8];
            float4 a1 = *(const float4*)&As[kk][ty * 8 + 4];
            float4 b0 = *(const float4*)&Bs[kk][tx * 8];
            float4 b1 = *(const float4*)&Bs[kk][tx * 8 + 4];
            float ar[8] = {a0.x, a0.y, a0.z, a0.w, a1.x, a1.y, a1.z, a1.w};
            float br[8] = {b0.x, b0.y, b0.z, b0.w, b1.x, b1.y, b1.z, b1.w};
#pragma unroll
            for (int i = 0; i < 8; i++)
#pragma unroll
                for (int j = 0; j < 8; j++) acc[i][j] = fmaf(ar[i], br[j], acc[i][j]);
        }
        __syncthreads();
    }

#pragma unroll
    for (int i = 0; i < 8; i++) {
        int row = m0 + ty * 8 + i;
#pragma unroll
        for (int jb = 0; jb < 8; jb += 4) {
            int col = n0 + tx * 8 + jb;
            float4 o;
            o.x = acc[i][jb + 0] + bias[col + 0];
            o.y = acc[i][jb + 1] + bias[col + 1];
            o.z = acc[i][jb + 2] + bias[col + 2];
            o.w = acc[i][jb + 3] + bias[col + 3];
            if (EPI == 0) {
                o.x = 0.5f * o.x * (1.0f + erff(o.x * 0.70710678118654752f));
                o.y = 0.5f * o.y * (1.0f + erff(o.y * 0.70710678118654752f));
                o.z = 0.5f * o.z * (1.0f + erff(o.z * 0.70710678118654752f));
                o.w = 0.5f * o.w * (1.0f + erff(o.w * 0.70710678118654752f));
            } else {
                float4 r4 = *(const float4*)(resid + (size_t)row * Ndim + col);
                o.x += r4.x; o.y += r4.y; o.z += r4.z; o.w += r4.w;
            }
            *(float4*)(out + (size_t)row * Ndim + col) = o;
        }
    }
}

// ---------------------------------------------------------------------------
extern "C" void kernel_launch(void* const* d_in, const int* in_sizes, int n_in,
                              void* d_out, int out_size)
{
    const float* q = (const float*)d_in[0];
    const float* k = (const float*)d_in[1];
    const float* v = (const float*)d_in[2];
    const float* fc1_w = (const float*)d_in[3];
    const float* fc1_b = (const float*)d_in[4];
    const float* fc2_w = (const float*)d_in[5];
    const float* fc2_b = (const float*)d_in[6];
    const float* ln1_w = (const float*)d_in[7];
    const float* ln1_b = (const float*)d_in[8];
    const float* ln2_w = (const float*)d_in[9];
    const float* ln2_b = (const float*)d_in[10];
    float* out = (float*)d_out;

    float *attn, *q2, *hbuf;
    cudaGetSymbolAddress((void**)&attn, g_attn);
    cudaGetSymbolAddress((void**)&q2, g_q2);
    cudaGetSymbolAddress((void**)&hbuf, g_h);

    cudaFuncSetAttribute(attn_kernel,
                         cudaFuncAttributeMaxDynamicSharedMemorySize, ATTN_SMEM);

    // 1) attention -> g_attn
    attn_kernel<<<dim3(N_ / 64, H_, B_), 256, ATTN_SMEM>>>(q, k, v, attn);

    // 2) q2 = LN1(q + attn)
    ln_kernel<<<M_, 128>>>(attn, q, ln1_w, ln1_b, q2);

    // 3) h = gelu(q2 @ fc1_w^T + fc1_b)
    gemm_kernel<0><<<dim3(HIDE_ / GBN, M_ / GBM), 256>>>(
        q2, fc1_w, fc1_b, nullptr, hbuf, M_, HIDE_, C_);

    // 4) g_attn = q2 + (h @ fc2_w^T + fc2_b)
    gemm_kernel<1><<<dim3(C_ / GBN, M_ / GBM), 256>>>(
        hbuf, fc2_w, fc2_b, q2, attn, M_, C_, HIDE_);

    // 5) out = LN2(g_attn)
    ln_kernel<<<M_, 128>>>(attn, nullptr, ln2_w, ln2_b, out);
}

// round 4
// speedup vs baseline: 5.2845x; 5.2845x over previous
#include <cuda_runtime.h>
#include <math.h>
#include <stdint.h>

#define B_ 4
#define N_ 2048
#define C_ 512
#define H_ 8
#define HD_ 64
#define HIDE_ 2048
#define M_ (B_ * N_)   // 8192 rows

// Scratch (device globals: no cudaMalloc allowed)
__device__ float g_attn[(size_t)M_ * C_];
__device__ float g_q2[(size_t)M_ * C_];
__device__ float g_h[(size_t)M_ * HIDE_];

// ---------------------------------------------------------------------------
// TF32 helpers
// ---------------------------------------------------------------------------
__device__ __forceinline__ uint32_t f2tf(float f) {
    uint32_t u;
    asm("cvt.rna.tf32.f32 %0, %1;" : "=r"(u) : "f"(f));
    return u;
}
__device__ __forceinline__ float f2tf_f(float f) {
    return __uint_as_float(f2tf(f));
}

__device__ __forceinline__ void mma8(float* d,
                                     uint32_t a0, uint32_t a1, uint32_t a2, uint32_t a3,
                                     uint32_t b0, uint32_t b1) {
    asm volatile(
        "mma.sync.aligned.m16n8k8.row.col.f32.tf32.tf32.f32 "
        "{%0,%1,%2,%3}, {%4,%5,%6,%7}, {%8,%9}, {%0,%1,%2,%3};"
        : "+f"(d[0]), "+f"(d[1]), "+f"(d[2]), "+f"(d[3])
        : "r"(a0), "r"(a1), "r"(a2), "r"(a3), "r"(b0), "r"(b1));
}

__device__ __forceinline__ void cp16(uint32_t smem_addr, const void* gptr) {
    asm volatile("cp.async.cg.shared.global [%0], [%1], 16;" ::
                 "r"(smem_addr), "l"(gptr));
}
__device__ __forceinline__ void cp_commit() {
    asm volatile("cp.async.commit_group;");
}

// ---------------------------------------------------------------------------
// Flash attention (TF32 mma). Block: 128 q rows, 4 warps x 32 rows.
// KV tiles of 64. smem: Qs[128][68], Ps[128][68], Ks[64][68], Vs[64][72].
// ---------------------------------------------------------------------------
#define AQS 68
#define AVS 72
#define ATTN_SMEM ((128 * AQS * 2 + 64 * AQS + 64 * AVS) * 4)

__global__ void __launch_bounds__(128)
attn_kernel(const float* __restrict__ q,
            const float* __restrict__ k,
            const float* __restrict__ v,
            float* __restrict__ out)
{
    extern __shared__ float sm[];
    float* Qs = sm;                      // [128][AQS]  q rows x d
    float* Ps = sm + 128 * AQS;          // [128][AQS]  q rows x kv
    float* Ks = sm + 2 * 128 * AQS;      // [64][AQS]   kv rows x d
    float* Vs = Ks + 64 * AQS;           // [64][AVS]   kv rows x d

    const int tid = threadIdx.x;
    const int lane = tid & 31;
    const int wid = tid >> 5;
    const int r0 = lane >> 2;
    const int c0 = lane & 3;

    const int b = blockIdx.z;
    const int h = blockIdx.y;
    const int q0 = blockIdx.x * 128;

    const float* Qg = q + (size_t)(b * N_ + q0) * C_ + h * HD_;
    const float* Kg = k + (size_t)b * N_ * C_ + h * HD_;
    const float* Vg = v + (size_t)b * N_ * C_ + h * HD_;

    // Stage Q (scaled by 1/8, tf32-rounded)
    for (int i = tid; i < 128 * 16; i += 128) {
        int row = i >> 4;
        int col = (i & 15) * 4;
        float4 t = *(const float4*)(Qg + (size_t)row * C_ + col);
        Qs[row * AQS + col + 0] = f2tf_f(t.x * 0.125f);
        Qs[row * AQS + col + 1] = f2tf_f(t.y * 0.125f);
        Qs[row * AQS + col + 2] = f2tf_f(t.z * 0.125f);
        Qs[row * AQS + col + 3] = f2tf_f(t.w * 0.125f);
    }

    float o[2][8][4];
    float mrow[2][2], lrow[2][2];
#pragma unroll
    for (int mt = 0; mt < 2; mt++) {
#pragma unroll
        for (int h2 = 0; h2 < 2; h2++) { mrow[mt][h2] = -1e30f; lrow[mt][h2] = 0.0f; }
#pragma unroll
        for (int dt = 0; dt < 8; dt++)
#pragma unroll
            for (int rr = 0; rr < 4; rr++) o[mt][dt][rr] = 0.0f;
    }

    const int qbase = wid * 32;

    for (int kt = 0; kt < N_ / 64; kt++) {
        __syncthreads();
        const float* Kt = Kg + (size_t)kt * 64 * C_;
        const float* Vt = Vg + (size_t)kt * 64 * C_;
        for (int i = tid; i < 64 * 16; i += 128) {
            int row = i >> 4;
            int col = (i & 15) * 4;
            float4 t = *(const float4*)(Kt + (size_t)row * C_ + col);
            Ks[row * AQS + col + 0] = f2tf_f(t.x);
            Ks[row * AQS + col + 1] = f2tf_f(t.y);
            Ks[row * AQS + col + 2] = f2tf_f(t.z);
            Ks[row * AQS + col + 3] = f2tf_f(t.w);
            float4 u = *(const float4*)(Vt + (size_t)row * C_ + col);
            Vs[row * AVS + col + 0] = f2tf_f(u.x);
            Vs[row * AVS + col + 1] = f2tf_f(u.y);
            Vs[row * AVS + col + 2] = f2tf_f(u.z);
            Vs[row * AVS + col + 3] = f2tf_f(u.w);
        }
        __syncthreads();

        // S = Q @ K^T
        float s[2][8][4];
#pragma unroll
        for (int mt = 0; mt < 2; mt++)
#pragma unroll
            for (int nt = 0; nt < 8; nt++)
#pragma unroll
                for (int rr = 0; rr < 4; rr++) s[mt][nt][rr] = 0.0f;

#pragma unroll
        for (int ks = 0; ks < 8; ks++) {
            int kc = ks * 8 + c0;
            uint32_t a[2][4];
#pragma unroll
            for (int mt = 0; mt < 2; mt++) {
                const float* Qr = Qs + (qbase + mt * 16 + r0) * AQS;
                a[mt][0] = __float_as_uint(Qr[kc]);
                a[mt][1] = __float_as_uint(Qr[8 * AQS + kc]);
                a[mt][2] = __float_as_uint(Qr[kc + 4]);
                a[mt][3] = __float_as_uint(Qr[8 * AQS + kc + 4]);
            }
#pragma unroll
            for (int nt = 0; nt < 8; nt++) {
                const float* Kr = Ks + (nt * 8 + r0) * AQS;
                uint32_t b0 = __float_as_uint(Kr[kc]);
                uint32_t b1 = __float_as_uint(Kr[kc + 4]);
                mma8(s[0][nt], a[0][0], a[0][1], a[0][2], a[0][3], b0, b1);
                mma8(s[1][nt], a[1][0], a[1][1], a[1][2], a[1][3], b0, b1);
            }
        }

        // Online softmax. Row half h2=0 -> regs {0,1}, h2=1 -> regs {2,3}.
#pragma unroll
        for (int mt = 0; mt < 2; mt++) {
#pragma unroll
            for (int h2 = 0; h2 < 2; h2++) {
                float mx = -1e30f;
#pragma unroll
                for (int nt = 0; nt < 8; nt++) {
                    mx = fmaxf(mx, fmaxf(s[mt][nt][h2 * 2], s[mt][nt][h2 * 2 + 1]));
                }
                mx = fmaxf(mx, __shfl_xor_sync(0xffffffffu, mx, 1));
                mx = fmaxf(mx, __shfl_xor_sync(0xffffffffu, mx, 2));
                float mnew = fmaxf(mrow[mt][h2], mx);
                float sum = 0.0f;
#pragma unroll
                for (int nt = 0; nt < 8; nt++) {
                    float p0 = __expf(s[mt][nt][h2 * 2] - mnew);
                    float p1 = __expf(s[mt][nt][h2 * 2 + 1] - mnew);
                    s[mt][nt][h2 * 2] = p0;
                    s[mt][nt][h2 * 2 + 1] = p1;
                    sum += p0 + p1;
                }
                sum += __shfl_xor_sync(0xffffffffu, sum, 1);
                sum += __shfl_xor_sync(0xffffffffu, sum, 2);
                float corr = __expf(mrow[mt][h2] - mnew);
                lrow[mt][h2] = lrow[mt][h2] * corr + sum;
                mrow[mt][h2] = mnew;
#pragma unroll
                for (int dt = 0; dt < 8; dt++) {
                    o[mt][dt][h2 * 2] *= corr;
                    o[mt][dt][h2 * 2 + 1] *= corr;
                }
            }
        }

        // Write P to smem (tf32-rounded). Per-warp private rows.
#pragma unroll
        for (int mt = 0; mt < 2; mt++) {
            int prow = qbase + mt * 16 + r0;
#pragma unroll
            for (int nt = 0; nt < 8; nt++) {
                float2 p0 = make_float2(f2tf_f(s[mt][nt][0]), f2tf_f(s[mt][nt][1]));
                *(float2*)&Ps[prow * AQS + nt * 8 + 2 * c0] = p0;
                float2 p1 = make_float2(f2tf_f(s[mt][nt][2]), f2tf_f(s[mt][nt][3]));
                *(float2*)&Ps[(prow + 8) * AQS + nt * 8 + 2 * c0] = p1;
            }
        }
        __syncwarp();

        // O += P @ V
#pragma unroll
        for (int ks = 0; ks < 8; ks++) {
            int kc = ks * 8 + c0;
            uint32_t a[2][4];
#pragma unroll
            for (int mt = 0; mt < 2; mt++) {
                const float* Pr = Ps + (qbase + mt * 16 + r0) * AQS;
                a[mt][0] = __float_as_uint(Pr[kc]);
                a[mt][1] = __float_as_uint(Pr[8 * AQS + kc]);
                a[mt][2] = __float_as_uint(Pr[kc + 4]);
                a[mt][3] = __float_as_uint(Pr[8 * AQS + kc + 4]);
            }
#pragma unroll
            for (int dt = 0; dt < 8; dt++) {
                uint32_t b0 = __float_as_uint(Vs[(ks * 8 + c0) * AVS + dt * 8 + r0]);
                uint32_t b1 = __float_as_uint(Vs[(ks * 8 + c0 + 4) * AVS + dt * 8 + r0]);
                mma8(o[0][dt], a[0][0], a[0][1], a[0][2], a[0][3], b0, b1);
                mma8(o[1][dt], a[1][0], a[1][1], a[1][2], a[1][3], b0, b1);
            }
        }
    }

    // Epilogue
#pragma unroll
    for (int mt = 0; mt < 2; mt++) {
        int row = q0 + qbase + mt * 16 + r0;
        float inv0 = 1.0f / lrow[mt][0];
        float inv1 = 1.0f / lrow[mt][1];
        float* O0 = out + (size_t)(b * N_ + row) * C_ + h * HD_;
        float* O1 = out + (size_t)(b * N_ + row + 8) * C_ + h * HD_;
#pragma unroll
        for (int dt = 0; dt < 8; dt++) {
            float2 t0 = make_float2(o[mt][dt][0] * inv0, o[mt][dt][1] * inv0);
            *(float2*)(O0 + dt * 8 + 2 * c0) = t0;
            float2 t1 = make_float2(o[mt][dt][2] * inv1, o[mt][dt][3] * inv1);
            *(float2*)(O1 + dt * 8 + 2 * c0) = t1;
        }
    }
}

// ---------------------------------------------------------------------------
// Fused (optional residual add) + LayerNorm. One block (128 thr) per row.
// ---------------------------------------------------------------------------
__global__ void ln_kernel(const float* __restrict__ x,
                          const float* __restrict__ res,
                          const float* __restrict__ w,
                          const float* __restrict__ bb,
                          float* __restrict__ out)
{
    const int row = blockIdx.x;
    const int tid = threadIdx.x;
    const int col = tid * 4;

    float4 a = *(const float4*)(x + (size_t)row * C_ + col);
    if (res != nullptr) {
        float4 r4 = *(const float4*)(res + (size_t)row * C_ + col);
        a.x += r4.x; a.y += r4.y; a.z += r4.z; a.w += r4.w;
    }
    float s = a.x + a.y + a.z + a.w;
    float ss = a.x * a.x + a.y * a.y + a.z * a.z + a.w * a.w;

#pragma unroll
    for (int off = 16; off >= 1; off >>= 1) {
        s += __shfl_xor_sync(0xffffffffu, s, off);
        ss += __shfl_xor_sync(0xffffffffu, ss, off);
    }
    __shared__ float red[8];
    int wid = tid >> 5;
    if ((tid & 31) == 0) { red[wid] = s; red[wid + 4] = ss; }
    __syncthreads();
    float tot = red[0] + red[1] + red[2] + red[3];
    float tot2 = red[4] + red[5] + red[6] + red[7];

    const float mean = tot * (1.0f / C_);
    const float var = tot2 * (1.0f / C_) - mean * mean;
    const float inv = rsqrtf(var + 1e-6f);

    float4 wv = *(const float4*)(w + col);
    float4 bv = *(const float4*)(bb + col);
    float4 o;
    o.x = (a.x - mean) * inv * wv.x + bv.x;
    o.y = (a.y - mean) * inv * wv.y + bv.y;
    o.z = (a.z - mean) * inv * wv.z + bv.z;
    o.w = (a.w - mean) * inv * wv.w + bv.w;
    *(float4*)(out + (size_t)row * C_ + col) = o;
}

// ---------------------------------------------------------------------------
// TF32 MMA GEMM: out[m][n] = epi( sum_k A[m][k]*W[n][k] + bias[n] )
// 128x128x32 tiles, 256 thr (8 warps 2x4, warp tile 64x32), cp.async 2-stage.
// EPI==0: exact GELU.  EPI==1: + resid.
// ---------------------------------------------------------------------------
#define GSK 36
#define GEMM_STAGE_FLOATS (2 * 128 * GSK)       // As + Bs per stage
#define GEMM_SMEM (2 * GEMM_STAGE_FLOATS * 4)   // 2 stages

template <int EPI>
__global__ void __launch_bounds__(256)
gemm_kernel(const float* __restrict__ A,
            const float* __restrict__ W,
            const float* __restrict__ bias,
            const float* __restrict__ resid,
            float* __restrict__ out,
            int Ndim, int Kdim)
{
    extern __shared__ float sm[];

    const int tid = threadIdx.x;
    const int lane = tid & 31;
    const int wid = tid >> 5;
    const int r0 = lane >> 2;
    const int c0 = lane & 3;
    const int wm = (wid >> 2) * 64;
    const int wn = (wid & 3) * 32;

    const int m0 = blockIdx.y * 128;
    const int n0 = blockIdx.x * 128;

    const float* Ab = A + (size_t)m0 * Kdim;
    const float* Wb = W + (size_t)n0 * Kdim;

    float acc[4][4][4];
#pragma unroll
    for (int mt = 0; mt < 4; mt++)
#pragma unroll
        for (int nt = 0; nt < 4; nt++)
#pragma unroll
            for (int rr = 0; rr < 4; rr++) acc[mt][nt][rr] = 0.0f;

    const int row_st = tid >> 3;            // 0..31 base pattern rows
    const int col_st = (tid & 7) * 4;       // 0,4,..28

    // stage loader: copies A[128][32], B[128][32] into stage s at k offset k0
    auto stage = [&](int s, int k0) {
        float* As = sm + s * GEMM_STAGE_FLOATS;
        float* Bs = As + 128 * GSK;
#pragma unroll
        for (int c = 0; c < 4; c++) {
            int row = c * 32 + row_st;
            uint32_t da = (uint32_t)__cvta_generic_to_shared(As + row * GSK + col_st);
            cp16(da, Ab + (size_t)row * Kdim + k0 + col_st);
            uint32_t db = (uint32_t)__cvta_generic_to_shared(Bs + row * GSK + col_st);
            cp16(db, Wb + (size_t)row * Kdim + k0 + col_st);
        }
    };

    auto compute = [&](int s) {
        const float* As = sm + s * GEMM_STAGE_FLOATS;
        const float* Bs = As + 128 * GSK;
#pragma unroll
        for (int ks = 0; ks < 4; ks++) {
            int kc = ks * 8 + c0;
            uint32_t af[4][4], bf[4][2];
#pragma unroll
            for (int mt = 0; mt < 4; mt++) {
                const float* Ar = As + (wm + mt * 16 + r0) * GSK;
                af[mt][0] = f2tf(Ar[kc]);
                af[mt][1] = f2tf(Ar[8 * GSK + kc]);
                af[mt][2] = f2tf(Ar[kc + 4]);
                af[mt][3] = f2tf(Ar[8 * GSK + kc + 4]);
            }
#pragma unroll
            for (int nt = 0; nt < 4; nt++) {
                const float* Br = Bs + (wn + nt * 8 + r0) * GSK;
                bf[nt][0] = f2tf(Br[kc]);
                bf[nt][1] = f2tf(Br[kc + 4]);
            }
#pragma unroll
            for (int mt = 0; mt < 4; mt++)
#pragma unroll
                for (int nt = 0; nt < 4; nt++)
                    mma8(acc[mt][nt], af[mt][0], af[mt][1], af[mt][2], af[mt][3],
                         bf[nt][0], bf[nt][1]);
        }
    };

    const int KT = Kdim / 32;
    stage(0, 0);
    cp_commit();

    for (int kt = 0; kt < KT; kt++) {
        if (kt + 1 < KT) {
            stage((kt + 1) & 1, (kt + 1) * 32);
            cp_commit();
            asm volatile("cp.async.wait_group 1;");
        } else {
            asm volatile("cp.async.wait_group 0;");
        }
        __syncthreads();
        compute(kt & 1);
        __syncthreads();
    }

    // Epilogue
#pragma unroll
    for (int mt = 0; mt < 4; mt++) {
        int row = m0 + wm + mt * 16 + r0;
#pragma unroll
        for (int half = 0; half < 2; half++) {
            int rrow = row + half * 8;
#pragma unroll
            for (int nt = 0; nt < 4; nt++) {
                int col = n0 + wn + nt * 8 + 2 * c0;
                float vx = acc[mt][nt][half * 2 + 0] + bias[col];
                float vy = acc[mt][nt][half * 2 + 1] + bias[col + 1];
                if (EPI == 0) {
                    vx = 0.5f * vx * (1.0f + erff(vx * 0.70710678118654752f));
                    vy = 0.5f * vy * (1.0f + erff(vy * 0.70710678118654752f));
                } else {
                    float2 r2 = *(const float2*)(resid + (size_t)rrow * Ndim + col);
                    vx += r2.x; vy += r2.y;
                }
                *(float2*)(out + (size_t)rrow * Ndim + col) = make_float2(vx, vy);
            }
        }
    }
}

// ---------------------------------------------------------------------------
extern "C" void kernel_launch(void* const* d_in, const int* in_sizes, int n_in,
                              void* d_out, int out_size)
{
    const float* q = (const float*)d_in[0];
    const float* k = (const float*)d_in[1];
    const float* v = (const float*)d_in[2];
    const float* fc1_w = (const float*)d_in[3];
    const float* fc1_b = (const float*)d_in[4];
    const float* fc2_w = (const float*)d_in[5];
    const float* fc2_b = (const float*)d_in[6];
    const float* ln1_w = (const float*)d_in[7];
    const float* ln1_b = (const float*)d_in[8];
    const float* ln2_w = (const float*)d_in[9];
    const float* ln2_b = (const float*)d_in[10];
    float* out = (float*)d_out;

    float *attn, *q2, *hbuf;
    cudaGetSymbolAddress((void**)&attn, g_attn);
    cudaGetSymbolAddress((void**)&q2, g_q2);
    cudaGetSymbolAddress((void**)&hbuf, g_h);

    cudaFuncSetAttribute(attn_kernel,
                         cudaFuncAttributeMaxDynamicSharedMemorySize, ATTN_SMEM);
    cudaFuncSetAttribute(gemm_kernel<0>,
                         cudaFuncAttributeMaxDynamicSharedMemorySize, GEMM_SMEM);
    cudaFuncSetAttribute(gemm_kernel<1>,
                         cudaFuncAttributeMaxDynamicSharedMemorySize, GEMM_SMEM);

    // 1) attention -> g_attn
    attn_kernel<<<dim3(N_ / 128, H_, B_), 128, ATTN_SMEM>>>(q, k, v, attn);

    // 2) q2 = LN1(q + attn)
    ln_kernel<<<M_, 128>>>(attn, q, ln1_w, ln1_b, q2);

    // 3) h = gelu(q2 @ fc1_w^T + fc1_b)
    gemm_kernel<0><<<dim3(HIDE_ / 128, M_ / 128), 256, GEMM_SMEM>>>(
        q2, fc1_w, fc1_b, nullptr, hbuf, HIDE_, C_);

    // 4) g_attn = q2 + (h @ fc2_w^T + fc2_b)
    gemm_kernel<1><<<dim3(C_ / 128, M_ / 128), 256, GEMM_SMEM>>>(
        hbuf, fc2_w, fc2_b, q2, attn, C_, HIDE_);

    // 5) out = LN2(g_attn)
    ln_kernel<<<M_, 128>>>(attn, nullptr, ln2_w, ln2_b, out);
}